// round 17
// baseline (speedup 1.0000x reference)
#include <cuda_runtime.h>
#include <cuda_bf16.h>
#include <cstdint>
#include <math.h>

#define TOK 1024
#define NE 8
#define HD 1024
#define ID 768
#define NPAIR (2*TOK)

#define STG 24576            // stage: A 16KB + B 8KB
#define OPB 16384            // B offset within stage

// ------------------------- device scratch (static, no allocs) -------------
__device__ int   g_cnt[NE];
__device__ int   g_bucket[NE][TOK];
__device__ float g_wt[NPAIR];

__device__ float xs[(size_t)TOK*HD];          // tf32-rounded x
__device__ float g_act[(size_t)NPAIR*ID];     // tf32-rounded activations

// persistent-scheduler state (reset by routing kernel every launch)
__device__ int g_next, g_total;
__device__ int g_items[2048];
__device__ int g1done[NE], g1need[NE];

// ------------------------- PTX helpers (baseline ISA only) ----------------
__device__ __forceinline__ uint32_t smem_u32(const void* p) {
    uint32_t a;
    asm("{ .reg .u64 t; cvta.to.shared.u64 t, %1; cvt.u32.u64 %0, t; }" : "=r"(a) : "l"(p));
    return a;
}
__device__ __forceinline__ void cp16(uint32_t dst, const void* src) {
    asm volatile("cp.async.cg.shared.global [%0], [%1], 16;" :: "r"(dst), "l"(src));
}
__device__ __forceinline__ void cp_commit() {
    asm volatile("cp.async.commit_group;");
}
__device__ __forceinline__ void ldsm4(uint32_t* r, uint32_t addr) {
    asm volatile("ldmatrix.sync.aligned.m8n8.x4.shared.b16 {%0,%1,%2,%3}, [%4];"
        : "=r"(r[0]), "=r"(r[1]), "=r"(r[2]), "=r"(r[3]) : "r"(addr));
}
__device__ __forceinline__ void mma_tf32(float* d, const uint32_t* a, uint32_t b0, uint32_t b1) {
    asm volatile("mma.sync.aligned.m16n8k8.row.col.f32.tf32.tf32.f32 "
        "{%0,%1,%2,%3}, {%4,%5,%6,%7}, {%8,%9}, {%0,%1,%2,%3};"
        : "+f"(d[0]), "+f"(d[1]), "+f"(d[2]), "+f"(d[3])
        : "r"(a[0]), "r"(a[1]), "r"(a[2]), "r"(a[3]), "r"(b0), "r"(b1));
}
__device__ __forceinline__ uint32_t to_tf32(float f) {
    uint32_t r;
    asm("cvt.rna.tf32.f32 %0, %1;" : "=r"(r) : "f"(f));
    return r;
}
__device__ __forceinline__ void sts128(uint32_t addr, uint4 v) {
    asm volatile("st.shared.v4.b32 [%0], {%1,%2,%3,%4};"
                 :: "r"(addr), "r"(v.x), "r"(v.y), "r"(v.z), "r"(v.w));
}

// ------------------------- routing + planner ------------------------------
__global__ void routing_kernel(const float* __restrict__ rl) {
    int t = threadIdx.x;
    if (t < NE) g_cnt[t] = 0;
    __syncthreads();
    float l[NE];
#pragma unroll
    for (int e = 0; e < NE; e++) l[e] = rl[t * NE + e];
    int i0 = 0; float v0 = l[0];
#pragma unroll
    for (int e = 1; e < NE; e++) if (l[e] > v0) { v0 = l[e]; i0 = e; }
    int i1 = -1; float v1 = -3.4e38f;
#pragma unroll
    for (int e = 0; e < NE; e++) if (e != i0 && l[e] > v1) { v1 = l[e]; i1 = e; }
    float e1 = expf(v1 - v0);
    float inv = 1.0f / (1.0f + e1);
    int p0 = 2 * t, p1 = 2 * t + 1;
    g_wt[p0] = inv;
    g_wt[p1] = e1 * inv;
    int pos0 = atomicAdd(&g_cnt[i0], 1); g_bucket[i0][pos0] = p0;
    int pos1 = atomicAdd(&g_cnt[i1], 1); g_bucket[i1][pos1] = p1;

    // ---- planner: phase1 tiles (n=32 gate+up pairs, 24/x-row), then phase2 ----
    __syncthreads();
    __shared__ int s_b1[NE + 1], s_b2[NE + 1];
    if (t == 0) {
        int b1 = 0, b2 = 0;
        for (int e = 0; e < NE; e++) {
            int yt = (g_cnt[e] + 127) >> 7;
            s_b1[e] = b1; s_b2[e] = b2;
            g1need[e] = yt * 24;          // 24 n-tiles of 32 in gemm1
            g1done[e] = 0;
            b1 += yt * 24;
            b2 += yt * 16;                // 16 n-tiles of 64 in gemm2
        }
        s_b1[NE] = b1; s_b2[NE] = b2;
        g_total = b1 + b2;
        g_next  = 0;
    }
    __syncthreads();
    int tot1 = s_b1[NE], tot2 = s_b2[NE];
    for (int i = t; i < tot1; i += TOK) {
        int e = 0;
        while (i >= s_b1[e + 1]) e++;
        int loc = i - s_b1[e];
        g_items[i] = (0 << 28) | (e << 24) | ((loc / 24) << 16) | (loc % 24);
    }
    for (int i = t; i < tot2; i += TOK) {
        int e = 0;
        while (i >= s_b2[e + 1]) e++;
        int loc = i - s_b2[e];
        g_items[tot1 + i] = (1 << 28) | (e << 24) | ((loc / 16) << 16) | (loc % 16);
    }
}

// ------------------- x prepass: tf32 rounding + zero out ------------------
__global__ void convert_x_kernel(const float* __restrict__ x, float* __restrict__ out) {
    size_t i4 = ((size_t)blockIdx.x * 256 + threadIdx.x) * 4;
    float4 v = *(const float4*)(x + i4);
    float4 o;
    o.x = __uint_as_float(to_tf32(v.x));
    o.y = __uint_as_float(to_tf32(v.y));
    o.z = __uint_as_float(to_tf32(v.z));
    o.w = __uint_as_float(to_tf32(v.w));
    *(float4*)(xs + i4) = o;
    *(float4*)(out + i4) = make_float4(0.f, 0.f, 0.f, 0.f);   // out: TOK*HD elems
}

// ===========================================================================
// Persistent fused GEMM kernel. 256 threads, 8 warps: mw = wid>>1 (4 x 32 m),
// nwp = wid&1 (2 x 32 n). Block tile 128x64, warp tile 32x32, acc[2][4][4].
// K-chunk 32 (128B rows), 2 stages of 24KB -> ~49KB smem => 2 CTAs/SM.
// A via cp.async; B register-staged (2 x uint4) w/ fused dequant + tf32.
// ===========================================================================
__global__ __launch_bounds__(256) void moe_gemms(
    const float* __restrict__ w13, const float* __restrict__ w13s,
    const float* __restrict__ w2,  const float* __restrict__ w2s,
    float* __restrict__ out)
{
    extern __shared__ __align__(16) char dynraw[];
    __shared__ int s_row[128];
    __shared__ int s_pair[128];
    __shared__ int s_item;

    int tid = threadIdx.x, wid = tid >> 5, lane = tid & 31;
    uint32_t dynb0 = smem_u32(dynraw);
    uint32_t dynb = (dynb0 + 1023u) & ~1023u;
    float* s_up = (float*)(dynraw + (dynb - dynb0));   // reuse stage smem post-loop

    int row0 = tid >> 3, piece = tid & 7;   // row0 0..31, 16B piece 0..7
    uint32_t asd0 = dynb + row0 * 128 + ((piece * 16) ^ ((row0 & 7) << 4));
    uint32_t bsd0 = asd0 + OPB;

    int mw = wid >> 1, nwp = wid & 1;
    uint32_t sw    = (lane & 7) << 4;
    uint32_t aBase = dynb + (uint32_t)(mw * 32 + ((lane >> 3) & 1) * 8 + (lane & 7)) * 128;
    uint32_t aK    = (lane >> 4) * 16;
    uint32_t bBase = dynb + OPB + (uint32_t)(nwp * 32 + (lane >> 4) * 8 + (lane & 7)) * 128;
    uint32_t bK    = ((lane >> 3) & 1) * 16;
    int g2l = lane >> 2, t2 = (lane & 3) * 2;

    for (;;) {
        if (tid == 0) {
            int idx = atomicAdd(&g_next, 1);
            s_item = (idx < g_total) ? g_items[idx] : -1;
        }
        __syncthreads();
        int item = s_item;
        __syncthreads();
        if (item < 0) break;
        int ph = item >> 28;
        int e  = (item >> 24) & 15;
        int m0 = ((item >> 16) & 255) * 128;
        int ntile = item & 65535;
        int Me = g_cnt[e];

        if (ph == 0) {
            // ============ GEMM1 tile: 128 x (32 gate + 32 up), K=1024 ============
            int n0g = ntile * 32;
            if (tid < 128) {
                int r = m0 + tid;
                int pr = (r < Me) ? g_bucket[e][r] : 0;
                s_pair[tid] = (r < Me) ? pr : -1;
                s_row[tid]  = pr >> 1;
            }
            __syncthreads();

            const float* asrc[4];
            const float* bgp[2];
            uint32_t bsoff[2];
#pragma unroll
            for (int it = 0; it < 4; it++)
                asrc[it] = xs + (size_t)s_row[row0 + it * 32] * HD + piece * 4;
#pragma unroll
            for (int it = 0; it < 2; it++) {
                int r = row0 + it * 32;
                int brow = (r < 32) ? (n0g + r) : (ID + n0g + (r - 32));
                bgp[it] = w13 + ((size_t)e * 2 * ID + brow) * HD + piece * 4;
                bsoff[it] = (uint32_t)(e * 2 * ID + brow) * (HD / 128);
            }

            uint4 breg[2]; float bs[2];
#pragma unroll
            for (int it = 0; it < 2; it++) breg[it] = *(const uint4*)bgp[it];
#pragma unroll
            for (int it = 0; it < 2; it++) bs[it] = w13s[bsoff[it]];
#pragma unroll
            for (int it = 0; it < 4; it++) cp16(asd0 + it * 4096, asrc[it]);
            cp_commit();

            float acc[2][4][4] = {};
            const int NC = HD / 32;   // 32
            for (int c = 0; c < NC; c++) {
                int st = c & 1;
#pragma unroll
                for (int it = 0; it < 2; it++) {
                    float s = bs[it];
                    uint4 r = breg[it], w;
                    w.x = to_tf32(__uint_as_float(r.x) * s);
                    w.y = to_tf32(__uint_as_float(r.y) * s);
                    w.z = to_tf32(__uint_as_float(r.z) * s);
                    w.w = to_tf32(__uint_as_float(r.w) * s);
                    sts128(bsd0 + it * 4096 + st * STG, w);
                }
                asm volatile("cp.async.wait_group 0;");
                __syncthreads();
                if (c + 1 < NC) {
                    uint32_t ko = (uint32_t)(c + 1) * 32;
#pragma unroll
                    for (int it = 0; it < 2; it++) breg[it] = *(const uint4*)(bgp[it] + ko);
                    if (((c + 1) & 3) == 0) {
                        int kb = (c + 1) >> 2;
#pragma unroll
                        for (int it = 0; it < 2; it++) bs[it] = w13s[bsoff[it] + kb];
                    }
                    uint32_t so = (uint32_t)((c + 1) & 1) * STG;
#pragma unroll
                    for (int it = 0; it < 4; it++) cp16(asd0 + it * 4096 + so, asrc[it] + ko);
                    cp_commit();
                }
                uint32_t ab = aBase + st * STG, bb = bBase + st * STG;
#pragma unroll
                for (int ks = 0; ks < 4; ks++) {
                    uint32_t A[2][4], B[2][4];
#pragma unroll
                    for (int mt = 0; mt < 2; mt++)
                        ldsm4(A[mt], ab + mt * 2048 + ((aK + ks * 32) ^ sw));
#pragma unroll
                    for (int p = 0; p < 2; p++)
                        ldsm4(B[p], bb + p * 2048 + ((bK + ks * 32) ^ sw));
#pragma unroll
                    for (int mt = 0; mt < 2; mt++)
#pragma unroll
                        for (int nt = 0; nt < 4; nt++)
                            mma_tf32(acc[mt][nt], A[mt], B[nt >> 1][(nt & 1) * 2], B[nt >> 1][(nt & 1) * 2 + 1]);
                }
                __syncthreads();
            }

            // epilogue: up warps (nwp==1) stash, gate warps fuse silu
            if (nwp == 1) {
#pragma unroll
                for (int mt = 0; mt < 2; mt++)
#pragma unroll
                    for (int nt = 0; nt < 4; nt++) {
                        int j = nt * 8 + t2;
                        int r = mw * 32 + mt * 16 + g2l;
                        *(float2*)&s_up[r * 34 + j]       = make_float2(acc[mt][nt][0], acc[mt][nt][1]);
                        *(float2*)&s_up[(r + 8) * 34 + j] = make_float2(acc[mt][nt][2], acc[mt][nt][3]);
                    }
            }
            __syncthreads();
            if (nwp == 0) {
#pragma unroll
                for (int mt = 0; mt < 2; mt++)
#pragma unroll
                    for (int nt = 0; nt < 4; nt++) {
                        int j = nt * 8 + t2;
                        int r0 = mw * 32 + mt * 16 + g2l, r1 = r0 + 8;
                        float2 u0 = *(float2*)&s_up[r0 * 34 + j];
                        float2 u1 = *(float2*)&s_up[r1 * 34 + j];
                        float g00 = acc[mt][nt][0], g01 = acc[mt][nt][1];
                        float g10 = acc[mt][nt][2], g11 = acc[mt][nt][3];
                        float a00 = u0.x * (g00 / (1.0f + __expf(-g00)));
                        float a01 = u0.y * (g01 / (1.0f + __expf(-g01)));
                        float a10 = u1.x * (g10 / (1.0f + __expf(-g10)));
                        float a11 = u1.y * (g11 / (1.0f + __expf(-g11)));
                        int p0 = s_pair[r0], p1 = s_pair[r1];
                        if (p0 >= 0)
                            *(float2*)(g_act + (size_t)p0 * ID + n0g + j) = make_float2(
                                __uint_as_float(to_tf32(a00)), __uint_as_float(to_tf32(a01)));
                        if (p1 >= 0)
                            *(float2*)(g_act + (size_t)p1 * ID + n0g + j) = make_float2(
                                __uint_as_float(to_tf32(a10)), __uint_as_float(to_tf32(a11)));
                    }
            }
            __threadfence();
            __syncthreads();
            if (tid == 0) atomicAdd(&g1done[e], 1);
        } else {
            // ============ GEMM2 tile: 128 x 64, K=768, atomic combine ============
            int n0 = ntile * 64;
            if (tid == 0) {
                int need = g1need[e];
                while (*(volatile int*)&g1done[e] < need) { }
            }
            __syncthreads();
            __threadfence();

            if (tid < 128) {
                int r = m0 + tid;
                int pr = (r < Me) ? g_bucket[e][r] : 0;
                s_pair[tid] = (r < Me) ? pr : -1;
                s_row[tid]  = pr;
            }
            __syncthreads();

            const float* asrc[4];
            const float* bgp[2];
            uint32_t bsoff[2];
#pragma unroll
            for (int it = 0; it < 4; it++)
                asrc[it] = g_act + (size_t)s_row[row0 + it * 32] * ID + piece * 4;
#pragma unroll
            for (int it = 0; it < 2; it++) {
                int r = row0 + it * 32;
                bgp[it] = w2 + ((size_t)e * HD + n0 + r) * ID + piece * 4;
                bsoff[it] = (uint32_t)(e * HD + n0 + r) * (ID / 128);
            }

            uint4 breg[2]; float bs[2];
#pragma unroll
            for (int it = 0; it < 2; it++) breg[it] = *(const uint4*)bgp[it];
#pragma unroll
            for (int it = 0; it < 2; it++) bs[it] = w2s[bsoff[it]];
#pragma unroll
            for (int it = 0; it < 4; it++) cp16(asd0 + it * 4096, asrc[it]);
            cp_commit();

            float acc[2][4][4] = {};
            const int NC = ID / 32;   // 24
            for (int c = 0; c < NC; c++) {
                int st = c & 1;
#pragma unroll
                for (int it = 0; it < 2; it++) {
                    float s = bs[it];
                    uint4 r = breg[it], w;
                    w.x = to_tf32(__uint_as_float(r.x) * s);
                    w.y = to_tf32(__uint_as_float(r.y) * s);
                    w.z = to_tf32(__uint_as_float(r.z) * s);
                    w.w = to_tf32(__uint_as_float(r.w) * s);
                    sts128(bsd0 + it * 4096 + st * STG, w);
                }
                asm volatile("cp.async.wait_group 0;");
                __syncthreads();
                if (c + 1 < NC) {
                    uint32_t ko = (uint32_t)(c + 1) * 32;
#pragma unroll
                    for (int it = 0; it < 2; it++) breg[it] = *(const uint4*)(bgp[it] + ko);
                    if (((c + 1) & 3) == 0) {
                        int kb = (c + 1) >> 2;
#pragma unroll
                        for (int it = 0; it < 2; it++) bs[it] = w2s[bsoff[it] + kb];
                    }
                    uint32_t so = (uint32_t)((c + 1) & 1) * STG;
#pragma unroll
                    for (int it = 0; it < 4; it++) cp16(asd0 + it * 4096 + so, asrc[it] + ko);
                    cp_commit();
                }
                uint32_t ab = aBase + st * STG, bb = bBase + st * STG;
#pragma unroll
                for (int ks = 0; ks < 4; ks++) {
                    uint32_t A[2][4], B[2][4];
#pragma unroll
                    for (int mt = 0; mt < 2; mt++)
                        ldsm4(A[mt], ab + mt * 2048 + ((aK + ks * 32) ^ sw));
#pragma unroll
                    for (int p = 0; p < 2; p++)
                        ldsm4(B[p], bb + p * 2048 + ((bK + ks * 32) ^ sw));
#pragma unroll
                    for (int mt = 0; mt < 2; mt++)
#pragma unroll
                        for (int nt = 0; nt < 4; nt++)
                            mma_tf32(acc[mt][nt], A[mt], B[nt >> 1][(nt & 1) * 2], B[nt >> 1][(nt & 1) * 2 + 1]);
                }
                __syncthreads();
            }

            // epilogue: weighted atomic accumulate directly into out
#pragma unroll
            for (int mt = 0; mt < 2; mt++)
#pragma unroll
                for (int nt = 0; nt < 4; nt++) {
                    int j = n0 + nwp * 32 + nt * 8 + t2;
                    int r0 = mw * 32 + mt * 16 + g2l, r1 = r0 + 8;
                    int p0 = s_pair[r0], p1 = s_pair[r1];
                    if (p0 >= 0) {
                        float wf = g_wt[p0];
                        float* dst = out + (size_t)(p0 >> 1) * HD + j;
                        atomicAdd(dst,     wf * acc[mt][nt][0]);
                        atomicAdd(dst + 1, wf * acc[mt][nt][1]);
                    }
                    if (p1 >= 0) {
                        float wf = g_wt[p1];
                        float* dst = out + (size_t)(p1 >> 1) * HD + j;
                        atomicAdd(dst,     wf * acc[mt][nt][2]);
                        atomicAdd(dst + 1, wf * acc[mt][nt][3]);
                    }
                }
            __syncthreads();
        }
    }
}

// ------------------------- launch -----------------------------------------
extern "C" void kernel_launch(void* const* d_in, const int* in_sizes, int n_in,
                              void* d_out, int out_size) {
    const float* x    = (const float*)d_in[0];
    const float* rl   = (const float*)d_in[1];
    const float* w13  = (const float*)d_in[2];
    const float* w13s = (const float*)d_in[3];
    const float* w2   = (const float*)d_in[4];
    const float* w2s  = (const float*)d_in[5];
    float* out = (float*)d_out;

    const int DSM = 2 * STG + 1024;   // 50.2 KB -> 2+ CTAs/SM
    cudaFuncSetAttribute(moe_gemms, cudaFuncAttributeMaxDynamicSharedMemorySize, DSM);

    routing_kernel<<<1, TOK>>>(rl);
    convert_x_kernel<<<(TOK * HD) / (256 * 4), 256>>>(x, out);

    moe_gemms<<<304, 256, DSM>>>(w13, w13s, w2, w2s, out);
}